// round 6
// baseline (speedup 1.0000x reference)
#include <cuda_runtime.h>
#include <cstdint>

// out[r,c] = x[r,c] * diag[c], 16384 x 2048 f32.
// Bulk-staged variant: each CTA copies a 64KB tile (8 full rows) GMEM->SMEM
// via cp.async.bulk (TMA path, full-line bursts), multiplies in SMEM, then
// bulk-stores SMEM->GMEM. Coarse same-direction bursts per CTA reduce DRAM
// read<->write bus-turnaround switching; ~3 CTAs/SM overlap load/compute/store.

#define TILE_BYTES 65536
#define TILE_F4    (TILE_BYTES / 16)   // 4096 float4
#define THREADS    256

__global__ __launch_bounds__(THREADS) void diag_bulk_kernel(
    const float* __restrict__ x,
    const float* __restrict__ d,
    float* __restrict__ out)
{
    extern __shared__ __align__(128) unsigned char smem[];
    uint32_t smem_base;
    asm("{ .reg .u64 t; cvta.to.shared.u64 t, %1; cvt.u32.u64 %0, t; }"
        : "=r"(smem_base) : "l"(smem));
    const uint32_t mbar = smem_base;          // 8B mbarrier
    const uint32_t tile = smem_base + 128;    // 64KB tile, 128B aligned

    const int tid = threadIdx.x;
    const size_t byte_off = (size_t)blockIdx.x * TILE_BYTES;

    if (tid == 0) {
        asm volatile("mbarrier.init.shared.b64 [%0], 1;" :: "r"(mbar) : "memory");
        asm volatile("mbarrier.arrive.expect_tx.shared.b64 _, [%0], %1;"
                     :: "r"(mbar), "r"(TILE_BYTES) : "memory");
        asm volatile(
            "cp.async.bulk.shared::cta.global.mbarrier::complete_tx::bytes "
            "[%0], [%1], %2, [%3];"
            :: "r"(tile), "l"((const char*)x + byte_off), "r"(TILE_BYTES),
               "r"(mbar) : "memory");
    }
    __syncthreads();  // mbarrier init visible to all before polling

    // Wait for TMA load (parity 0)
    {
        uint32_t done;
        asm volatile(
            "{\n\t.reg .pred p;\n\t"
            "mbarrier.try_wait.parity.acquire.cta.shared::cta.b64 p, [%1], 0;\n\t"
            "selp.b32 %0, 1, 0, p;\n\t}"
            : "=r"(done) : "r"(mbar) : "memory");
        if (!done) {
            asm volatile(
                "{\n\t.reg .pred P1;\n\t"
                "W%=:\n\t"
                "mbarrier.try_wait.parity.acquire.cta.shared::cta.b64 P1, [%0], 0, 0x989680;\n\t"
                "@P1 bra.uni D%=;\n\t"
                "bra.uni W%=;\n\t"
                "D%=:\n\t}"
                :: "r"(mbar) : "memory");
        }
    }

    // Multiply in SMEM: 4096 float4 / 256 threads = 16 per thread.
    // Tile starts on a row boundary (8 rows/tile) -> col4 of element j = j & 511.
    float4* tp = (float4*)(smem + 128);
    const float4* dp4 = (const float4*)d;
    #pragma unroll
    for (int k = 0; k < 16; k++) {
        int j = tid + k * THREADS;
        float4 v = tp[j];
        float4 s = __ldg(&dp4[j & 511]);
        v.x *= s.x; v.y *= s.y; v.z *= s.z; v.w *= s.w;
        tp[j] = v;
    }
    __syncthreads();

    if (tid == 0) {
        asm volatile("fence.proxy.async.shared::cta;" ::: "memory");
        asm volatile(
            "cp.async.bulk.global.shared::cta.bulk_group [%0], [%1], %2;"
            :: "l"((char*)out + byte_off), "r"(tile), "r"(TILE_BYTES) : "memory");
        asm volatile("cp.async.bulk.commit_group;" ::: "memory");
        asm volatile("cp.async.bulk.wait_group 0;" ::: "memory");  // smem must outlive store
    }
    __syncthreads();
}

extern "C" void kernel_launch(void* const* d_in, const int* in_sizes, int n_in,
                              void* d_out, int out_size) {
    const float* x = (const float*)d_in[0];
    const float* d = (const float*)d_in[1];
    float* out = (float*)d_out;

    static bool attr_set = false;
    if (!attr_set) {
        cudaFuncSetAttribute(diag_bulk_kernel,
                             cudaFuncAttributeMaxDynamicSharedMemorySize,
                             TILE_BYTES + 256);
        attr_set = true;
    }

    // 128 MB / 64 KB = 2048 tiles, exact (8 rows per tile)
    const int blocks = (16384 * 2048 * 4) / TILE_BYTES;  // 2048
    diag_bulk_kernel<<<blocks, THREADS, TILE_BYTES + 256>>>(x, d, out);
}

// round 7
// speedup vs baseline: 1.0397x; 1.0397x over previous
#include <cuda_runtime.h>
#include <cstdint>

// out[r, c] = x[r, c] * diag[c], x: 16384 x 2048 f32.
// Final form: pure HBM-streaming kernel at the measured mixed-r/w HBM wall
// (~6.2 TB/s sustained across graph replays; 268 MB compulsory traffic).
//   - 256-bit (v8.f32) accesses: 1024B/warp/access, max DRAM burst size
//   - 2 independent front-batched v8 loads per thread (MLP_p1 = 2, 2KB/warp
//     in flight at issue)
//   - .cs (evict-first) both directions: single-touch stream, default-policy
//     variants measured equal-or-better than .wt / evict_last hints
// Each thread handles 2 chunks of 8 floats in the same column, 2 consecutive
// rows apart (1 row = 2048 floats), so one ld.nc of diag serves both.

#define ROW_F 2048u

__global__ __launch_bounds__(256) void diag_scale_kernel(
    const float* __restrict__ x,
    const float* __restrict__ d,
    float* __restrict__ out)
{
    unsigned int t = blockIdx.x * 256u + threadIdx.x;     // 0 .. 2,097,151
    unsigned int col8 = (t & 255u) * 8u;                  // float column of chunk
    unsigned int rowpair = t >> 8;                        // pair of rows
    size_t base = (size_t)rowpair * (2u * ROW_F) + col8;

    const float* xp0 = x + base;
    const float* xp1 = x + base + ROW_F;
    float*       op0 = out + base;
    float*       op1 = out + base + ROW_F;
    const float* dp  = d + col8;

    float a0,a1,a2,a3,a4,a5,a6,a7;
    float b0,b1,b2,b3,b4,b5,b6,b7;
    asm volatile(
        "ld.global.cs.v8.f32 {%0,%1,%2,%3,%4,%5,%6,%7}, [%8];"
        : "=f"(a0),"=f"(a1),"=f"(a2),"=f"(a3),
          "=f"(a4),"=f"(a5),"=f"(a6),"=f"(a7)
        : "l"(xp0));
    asm volatile(
        "ld.global.cs.v8.f32 {%0,%1,%2,%3,%4,%5,%6,%7}, [%8];"
        : "=f"(b0),"=f"(b1),"=f"(b2),"=f"(b3),
          "=f"(b4),"=f"(b5),"=f"(b6),"=f"(b7)
        : "l"(xp1));

    float s0,s1,s2,s3,s4,s5,s6,s7;
    asm volatile(
        "ld.global.nc.v8.f32 {%0,%1,%2,%3,%4,%5,%6,%7}, [%8];"
        : "=f"(s0),"=f"(s1),"=f"(s2),"=f"(s3),
          "=f"(s4),"=f"(s5),"=f"(s6),"=f"(s7)
        : "l"(dp));

    a0*=s0; a1*=s1; a2*=s2; a3*=s3; a4*=s4; a5*=s5; a6*=s6; a7*=s7;
    b0*=s0; b1*=s1; b2*=s2; b3*=s3; b4*=s4; b5*=s5; b6*=s6; b7*=s7;

    asm volatile(
        "st.global.cs.v8.f32 [%0], {%1,%2,%3,%4,%5,%6,%7,%8};"
        :: "l"(op0),
           "f"(a0),"f"(a1),"f"(a2),"f"(a3),
           "f"(a4),"f"(a5),"f"(a6),"f"(a7)
        : "memory");
    asm volatile(
        "st.global.cs.v8.f32 [%0], {%1,%2,%3,%4,%5,%6,%7,%8};"
        :: "l"(op1),
           "f"(b0),"f"(b1),"f"(b2),"f"(b3),
           "f"(b4),"f"(b5),"f"(b6),"f"(b7)
        : "memory");
}

extern "C" void kernel_launch(void* const* d_in, const int* in_sizes, int n_in,
                              void* d_out, int out_size) {
    const float* x = (const float*)d_in[0];
    const float* d = (const float*)d_in[1];
    float* out = (float*)d_out;

    // 16384*2048 floats / 16 per thread = 2,097,152 threads -> 8192 blocks
    const int threads = 256;
    const int blocks = (16384 * 2048 / 16) / threads;  // 8192, exact

    diag_scale_kernel<<<blocks, threads>>>(x, d, out);
}